// round 9
// baseline (speedup 1.0000x reference)
#include <cuda_runtime.h>
#include <stdint.h>

// Problem constants (fixed by setup_inputs)
#define NN     4264    // all_node_num
#define BB     256     // batch
#define NGRP   8       // color groups
#define GSZ    533     // nodes per group
#define GSZPAD 536     // padded slot stride (536*4 and 536*8 are multiples of 16)
#define FIXED  28      // CSR entries per node (zero-padded); P(deg>28) ~ 7e-4
#define NPAIR  (FIXED/2)
#define MAXD   48      // hard cap on stored degree
#define MAXS   128     // max sweeps supported
#define TPB    544     // 17 warps: one node per thread (533 active)

#define COLS_BYTES (NPAIR * GSZPAD * 4)       // 30016 (multiple of 16)
#define VALS_BYTES (NPAIR * GSZPAD * 8)       // 60032 (multiple of 16)
#define STAGE_BYTES (COLS_BYTES + VALS_BYTES)

// Dynamic smem layout (all region offsets multiples of 16)
#define SM_MBAR   0
#define SM_MSH    16
#define SM_SKEY   (SM_MSH + NN * 4)                       // 17072
#define SM_COLS   (SM_SKEY + MAXS * NGRP * 8)             // 25264
#define SM_VALS   (SM_COLS + 2 * COLS_BYTES)              // 85296
#define SM_TOTAL  (SM_VALS + 2 * VALS_BYTES)              // 205360 (<227KB opt-in)

// Scratch (static device globals — no allocation)
__device__ int      d_deg[NN];
__device__ uint2    d_csr[NN][MAXD];              // overflow entries (k >= FIXED); rest 0
__device__ __align__(16) uint32_t d_colP[NGRP * NPAIR * GSZPAD]; // [g][j][slot]
__device__ __align__(16) float2   d_valP[NGRP * NPAIR * GSZPAD]; // [g][j][slot]

// ---------------------------------------------------------------------------
// Threefry-2x32 (20 rounds), bit-exact vs jax._src.prng.threefry2x32
// ---------------------------------------------------------------------------
__device__ __forceinline__ void tf2x32(uint32_t k0, uint32_t k1,
                                       uint32_t x0, uint32_t x1,
                                       uint32_t& o0, uint32_t& o1) {
    uint32_t ks2 = k0 ^ k1 ^ 0x1BD11BDAu;
    x0 += k0; x1 += k1;
#define TFR(r) { x0 += x1; x1 = __funnelshift_l(x1, x1, r); x1 ^= x0; }
    TFR(13) TFR(15) TFR(26) TFR(6)
    x0 += k1;  x1 += ks2 + 1u;
    TFR(17) TFR(29) TFR(16) TFR(24)
    x0 += ks2; x1 += k0 + 2u;
    TFR(13) TFR(15) TFR(26) TFR(6)
    x0 += k0;  x1 += k1 + 3u;
    TFR(17) TFR(29) TFR(16) TFR(24)
    x0 += k1;  x1 += ks2 + 4u;
    TFR(13) TFR(15) TFR(26) TFR(6)
    x0 += ks2; x1 += k0 + 5u;
#undef TFR
    o0 = x0; o1 = x1;
}

// XLA's f32 tanh rational approximation (Eigen-derived), FMA Horner.
__device__ __forceinline__ float tanh_xla(float x) {
    if (fabsf(x) < 0.0004f) return x;
    float xc = fmaxf(-7.90531110763549805f, fminf(7.90531110763549805f, x));
    float x2 = xc * xc;
    float p = -2.76076847742355e-16f;
    p = fmaf(p, x2,  2.00018790482477e-13f);
    p = fmaf(p, x2, -8.60467152213735e-11f);
    p = fmaf(p, x2,  5.12229709037114e-08f);
    p = fmaf(p, x2,  1.48572235717979e-05f);
    p = fmaf(p, x2,  6.37261928875436e-04f);
    p = fmaf(p, x2,  4.89352455891786e-03f);
    p = xc * p;
    float q = 1.19825839466702e-06f;
    q = fmaf(q, x2,  1.18534705686654e-04f);
    q = fmaf(q, x2,  2.26843463243900e-03f);
    q = fmaf(q, x2,  4.89352518554385e-03f);
    return p / q;
}

// bf16x2 pack/unpack: spins are {-1,0,+1} (zero low-16 mantissa) -> EXACT.
__device__ __forceinline__ uint32_t pack2(float a, float b) {
    return __byte_perm(__float_as_uint(a), __float_as_uint(b), 0x7632);
}
__device__ __forceinline__ float unpack_lo(uint32_t w) { return __uint_as_float(w << 16); }
__device__ __forceinline__ float unpack_hi(uint32_t w) { return __uint_as_float(w & 0xFFFF0000u); }

// ---- mbarrier / bulk-copy PTX helpers ----
__device__ __forceinline__ uint32_t smem_u32(const void* p) {
    return (uint32_t)__cvta_generic_to_shared(p);
}
__device__ __forceinline__ void mbar_init(uint32_t a, uint32_t cnt) {
    asm volatile("mbarrier.init.shared.b64 [%0], %1;" :: "r"(a), "r"(cnt) : "memory");
}
__device__ __forceinline__ void mbar_expect_tx(uint32_t a, uint32_t bytes) {
    asm volatile("mbarrier.arrive.expect_tx.shared.b64 _, [%0], %1;"
                 :: "r"(a), "r"(bytes) : "memory");
}
__device__ __forceinline__ void bulk_g2s(uint32_t dst, const void* src,
                                         uint32_t bytes, uint32_t mbar) {
    asm volatile(
        "cp.async.bulk.shared::cluster.global.mbarrier::complete_tx::bytes "
        "[%0], [%1], %2, [%3];"
        :: "r"(dst), "l"(src), "r"(bytes), "r"(mbar) : "memory");
}
__device__ __forceinline__ void mbar_wait(uint32_t a, uint32_t parity) {
    asm volatile(
        "{\n\t.reg .pred P;\n"
        "LW_%=:\n\t"
        "mbarrier.try_wait.parity.acquire.cta.shared::cta.b64 P, [%0], %1, 0x989680;\n\t"
        "@P bra.uni LD_%=;\n\t"
        "bra.uni LW_%=;\n"
        "LD_%=:\n\t}"
        :: "r"(a), "r"(parity) : "memory");
}

// ---------------------------------------------------------------------------
// Prep: dense J -> paired transposed split CSR. One warp per group-slot t;
// row = groups[t]. Ascending column order preserved (== reference order).
//   k <  FIXED -> d_colP/d_valP halves (zero-padded)
//   k >= FIXED -> d_csr[row][k]  (rare overflow; untouched slots stay 0)
// ---------------------------------------------------------------------------
__global__ void csr_kernel(const float* __restrict__ J,
                           const int* __restrict__ groups) {
    int t = (int)((blockIdx.x * blockDim.x + threadIdx.x) >> 5);
    if (t >= NN) return;
    int lane = threadIdx.x & 31;

    int g    = t / GSZ;
    int slot = t - g * GSZ;
    int row  = groups[t];
    uint16_t* cb = reinterpret_cast<uint16_t*>(d_colP);  // half index = 2*idx + (p&1)
    float*    vb = reinterpret_cast<float*>(d_valP);
    const size_t gbase = (size_t)g * NPAIR * GSZPAD;

    const float4* Jr = reinterpret_cast<const float4*>(J + (size_t)row * NN);
    const int NV4 = NN / 4;                       // 1066 (NN % 4 == 0)

    int count = 0;
    for (int q0 = 0; q0 < NV4; q0 += 32) {
        int q = q0 + lane;
        float4 v = (q < NV4) ? Jr[q] : make_float4(0.f, 0.f, 0.f, 0.f);
        int n = (v.x != 0.f) + (v.y != 0.f) + (v.z != 0.f) + (v.w != 0.f);
        int incl = n;
        #pragma unroll
        for (int d = 1; d < 32; d <<= 1) {
            int o = __shfl_up_sync(0xffffffffu, incl, d);
            if (lane >= d) incl += o;
        }
        int p = count + incl - n;                 // exclusive offset
        int c = q * 4;
        #define EMIT(val, col)                                                  \
            if ((val) != 0.f) {                                                 \
                if (p < FIXED) {                                                \
                    size_t ix = (gbase + (size_t)(p >> 1) * GSZPAD + slot) * 2 + (p & 1); \
                    cb[ix] = (uint16_t)(col);                                   \
                    vb[ix] = (val);                                             \
                } else if (p < MAXD) {                                          \
                    d_csr[row][p] =                                             \
                        make_uint2((uint32_t)(col), __float_as_uint(val));      \
                }                                                               \
                ++p;                                                            \
            }
        EMIT(v.x, c + 0) EMIT(v.y, c + 1) EMIT(v.z, c + 2) EMIT(v.w, c + 3)
        #undef EMIT
        count += __shfl_sync(0xffffffffu, incl, 31);
    }
    for (int k = count + lane; k < FIXED; k += 32) {   // exact +0 padding
        size_t ix = (gbase + (size_t)(k >> 1) * GSZPAD + slot) * 2 + (k & 1);
        cb[ix] = 0; vb[ix] = 0.0f;
    }
    if (lane == 0) d_deg[row] = (count < MAXD) ? count : MAXD;
}

// ---------------------------------------------------------------------------
// Main: one CTA per PAIR of batch rows; spins in SMEM packed bf16x2.
// CSR stream double-buffered through SMEM via cp.async.bulk + mbarrier,
// prefetched one phase ahead. Overflow (deg>FIXED) entries prefetched at
// phase START (MLP-4 predicated loads, hidden under the RNG) and applied
// after the main loop, preserving ascending-column fmaf order exactly.
// ---------------------------------------------------------------------------
__global__ void __launch_bounds__(TPB, 1)
gibbs_kernel(const float* __restrict__ m_in, const float* __restrict__ H,
             const int* __restrict__ groups, const int* __restrict__ sn,
             float* __restrict__ m_out) {
    extern __shared__ uint8_t sm[];
    uint32_t* msh   = reinterpret_cast<uint32_t*>(sm + SM_MSH);
    uint32_t* skey  = reinterpret_cast<uint32_t*>(sm + SM_SKEY);   // [p][2]
    uint32_t* scols = reinterpret_cast<uint32_t*>(sm + SM_COLS);   // 2 x NPAIR*GSZPAD
    float2*   svals = reinterpret_cast<float2*>(sm + SM_VALS);     // 2 x NPAIR*GSZPAD

    const uint32_t mbarA = smem_u32(sm + SM_MBAR);                 // mbar[2]
    const uint32_t colsA = smem_u32(sm + SM_COLS);
    const uint32_t valsA = smem_u32(sm + SM_VALS);

    const int b0  = 2 * blockIdx.x;
    const int b1  = b0 + 1;
    const int tid = threadIdx.x;

    int S = *sn; if (S > MAXS) S = MAXS; if (S < 0) S = 0;
    const int P = S * NGRP;

    for (int i = tid; i < NN; i += TPB)
        msh[i] = pack2(m_in[(size_t)b0 * NN + i], m_in[(size_t)b1 * NN + i]);

    // (sweep, group) keys: iter = tf(key42,(0,s)); group = tf(iter,(0,g))
    for (int u = tid; u < P; u += TPB) {
        int s = u / NGRP, g = u - s * NGRP;
        uint32_t ik0, ik1, gk0, gk1;
        tf2x32(0u, 42u, 0u, (uint32_t)s, ik0, ik1);
        tf2x32(ik0, ik1, 0u, (uint32_t)g, gk0, gk1);
        skey[2 * u + 0] = gk0; skey[2 * u + 1] = gk1;
    }

    // per-thread register cache per group
    const bool act = (tid < GSZ);
    int   nd[NGRP];
    float hh[NGRP];
    int   dg[NGRP];
    #pragma unroll
    for (int g = 0; g < NGRP; ++g) {
        int node = act ? groups[g * GSZ + tid] : 0;
        nd[g] = node;
        hh[g] = act ? H[node] : 0.0f;
        dg[g] = act ? d_deg[node] : 0;
    }

    if (tid == 0) { mbar_init(mbarA, 1); mbar_init(mbarA + 8, 1); }
    __syncthreads();

    // prologue: stage phase 0 into buffer 0
    if (tid == 0 && P > 0) {
        mbar_expect_tx(mbarA, STAGE_BYTES);
        bulk_g2s(colsA, d_colP, COLS_BYTES, mbarA);
        bulk_g2s(valsA, d_valP, VALS_BYTES, mbarA);
    }

    const uint32_t c0 = (uint32_t)(b0 * GSZ + tid);
    const uint32_t c1 = c0 + (uint32_t)GSZ;

    for (int s = 0; s < S; ++s) {
        #pragma unroll
        for (int g = 0; g < NGRP; ++g) {
            const int p = s * NGRP + g;
            // stage phase p+1 into the other buffer
            if (tid == 0 && p + 1 < P) {
                const int pn = p + 1, gn = pn & 7, bn = pn & 1;
                const uint32_t mb = mbarA + 8u * bn;
                mbar_expect_tx(mb, STAGE_BYTES);
                bulk_g2s(colsA + (uint32_t)bn * COLS_BYTES,
                         d_colP + (size_t)gn * NPAIR * GSZPAD, COLS_BYTES, mb);
                bulk_g2s(valsA + (uint32_t)bn * VALS_BYTES,
                         d_valP + (size_t)gn * NPAIR * GSZPAD, VALS_BYTES, mb);
            }

            uint32_t packed = 0u;
            int node = nd[g];
            int td   = dg[g];

            // overflow prefetch FIRST (rare; latency hidden under the RNG).
            // Unwritten d_csr slots are zero => exact +0 fmaf no-ops.
            uint2 ov0 = make_uint2(0u, 0u), ov1 = ov0, ov2 = ov0, ov3 = ov0;
            if (td > FIXED) {
                const uint2* ce = d_csr[node];
                ov0 = ce[FIXED + 0];
                ov1 = ce[FIXED + 1];
                ov2 = ce[FIXED + 2];
                ov3 = ce[FIXED + 3];
            }

            // wait for this phase's staged data (parity = use_count & 1)
            mbar_wait(mbarA + 8u * (p & 1), (uint32_t)((p >> 1) & 1));

            if (act) {
                const uint32_t k0 = skey[2 * p + 0];
                const uint32_t k1 = skey[2 * p + 1];
                uint32_t ya, yb, yc, yd;
                tf2x32(k0, k1, 0u, c0, ya, yb);
                tf2x32(k0, k1, 0u, c1, yc, yd);
                float r0 = (__uint_as_float(((ya ^ yb) >> 9) | 0x3f800000u) - 1.0f) * 2.0f - 1.0f;
                float r1 = (__uint_as_float(((yc ^ yd) >> 9) | 0x3f800000u) - 1.0f) * 2.0f - 1.0f;

                const uint32_t* sc = scols + (size_t)(p & 1) * NPAIR * GSZPAD + tid;
                const float2*   sv = svals + (size_t)(p & 1) * NPAIR * GSZPAD + tid;
                float a0 = 0.f, a1 = 0.f;
                #pragma unroll
                for (int j = 0; j < NPAIR; ++j) {
                    uint32_t cp2 = sc[j * GSZPAD];
                    float2   vv  = sv[j * GSZPAD];
                    uint32_t w0  = msh[cp2 & 0xFFFFu];
                    a0 = fmaf(vv.x, unpack_lo(w0), a0);
                    a1 = fmaf(vv.x, unpack_hi(w0), a1);
                    uint32_t w1  = msh[cp2 >> 16];
                    a0 = fmaf(vv.y, unpack_lo(w1), a0);
                    a1 = fmaf(vv.y, unpack_hi(w1), a1);
                }
                if (td > FIXED) {                  // ~3 nodes in the whole graph
                    #define APPLY(e) {                                     \
                        uint32_t w = msh[(e).x];                           \
                        float  vv  = __uint_as_float((e).y);               \
                        a0 = fmaf(vv, unpack_lo(w), a0);                   \
                        a1 = fmaf(vv, unpack_hi(w), a1); }
                    APPLY(ov0) APPLY(ov1) APPLY(ov2) APPLY(ov3)
                    #undef APPLY
                    if (td > FIXED + 4) {          // vanishing probability
                        for (int k = FIXED + 4; k < td; ++k) {
                            uint2 e = d_csr[node][k];
                            uint32_t w = msh[e.x];
                            float  vv  = __uint_as_float(e.y);
                            a0 = fmaf(vv, unpack_lo(w), a0);
                            a1 = fmaf(vv, unpack_hi(w), a1);
                        }
                    }
                }
                float d0 = tanh_xla(a0 + hh[g]) - r0;
                float d1 = tanh_xla(a1 + hh[g]) - r1;
                float s0 = (d0 > 0.f) ? 1.f : ((d0 < 0.f) ? -1.f : 0.f);
                float s1 = (d1 > 0.f) ? 1.f : ((d1 < 0.f) ? -1.f : 0.f);
                packed = pack2(s0, s1);            // exact for {-1,0,1}
            }
            __syncthreads();                      // all reads done
            if (act) msh[node] = packed;
            __syncthreads();                      // writes visible
        }
    }

    for (int i = tid; i < NN; i += TPB) {
        uint32_t w = msh[i];
        m_out[(size_t)b0 * NN + i] = unpack_lo(w);
        m_out[(size_t)b1 * NN + i] = unpack_hi(w);
    }
}

// ---------------------------------------------------------------------------
extern "C" void kernel_launch(void* const* d_in, const int* in_sizes, int n_in,
                              void* d_out, int out_size) {
    const float* m      = (const float*)d_in[0];
    const float* J      = (const float*)d_in[1];
    const float* H      = (const float*)d_in[2];
    const int*   groups = (const int*)  d_in[3];
    const int*   sn     = (const int*)  d_in[4];

    static int smem_set = 0;
    if (!smem_set) {
        cudaFuncSetAttribute(gibbs_kernel,
                             cudaFuncAttributeMaxDynamicSharedMemorySize, SM_TOTAL);
        smem_set = 1;
    }

    csr_kernel<<<(NN + 7) / 8, 256>>>(J, groups);    // 1 warp per group-slot
    gibbs_kernel<<<BB / 2, TPB, SM_TOTAL>>>(m, H, groups, sn, (float*)d_out);
}

// round 10
// speedup vs baseline: 1.0348x; 1.0348x over previous
#include <cuda_runtime.h>
#include <stdint.h>

// Problem constants (fixed by setup_inputs)
#define NN     4264    // all_node_num
#define BB     256     // batch
#define NGRP   8       // color groups
#define GSZ    533     // nodes per group
#define GSZPAD 536     // padded slot stride (keeps every region 16B-aligned)
#define FIXED  24      // CSR entries per node (zero-padded)
#define NQUAD  (FIXED/4)
#define MAXD   48      // hard cap on stored degree
#define MAXS   128     // max sweeps supported
#define TPB    544     // 17 warps: one node per thread (533 active)

#define COLS_BYTES (NQUAD * GSZPAD * 8)       // 25728 (uint2 per quad-slot), %16==0
#define VALS_BYTES (NQUAD * GSZPAD * 16)      // 51456 (float4 per quad-slot), %16==0
#define STAGE_BYTES (COLS_BYTES + VALS_BYTES)

// Dynamic smem layout (all region offsets multiples of 16)
#define SM_MBAR   0
#define SM_MSH    16
#define SM_SKEY   (SM_MSH + NN * 4)                       // 17072
#define SM_COLS   (SM_SKEY + MAXS * NGRP * 8)             // 25264
#define SM_VALS   (SM_COLS + 2 * COLS_BYTES)              // 76720
#define SM_TOTAL  (SM_VALS + 2 * VALS_BYTES)              // 179632 (<227KB opt-in)

// Scratch (static device globals — no allocation)
__device__ int      d_deg[NN];
__device__ uint2    d_csr[NN][MAXD];              // overflow entries (k >= FIXED); rest 0
__device__ __align__(16) uint16_t d_colQ[NGRP * NQUAD * GSZPAD * 4]; // [g][q][slot][4]
__device__ __align__(16) float    d_valQ[NGRP * NQUAD * GSZPAD * 4]; // [g][q][slot][4]

// ---------------------------------------------------------------------------
// Threefry-2x32 (20 rounds), bit-exact vs jax._src.prng.threefry2x32
// ---------------------------------------------------------------------------
__device__ __forceinline__ void tf2x32(uint32_t k0, uint32_t k1,
                                       uint32_t x0, uint32_t x1,
                                       uint32_t& o0, uint32_t& o1) {
    uint32_t ks2 = k0 ^ k1 ^ 0x1BD11BDAu;
    x0 += k0; x1 += k1;
#define TFR(r) { x0 += x1; x1 = __funnelshift_l(x1, x1, r); x1 ^= x0; }
    TFR(13) TFR(15) TFR(26) TFR(6)
    x0 += k1;  x1 += ks2 + 1u;
    TFR(17) TFR(29) TFR(16) TFR(24)
    x0 += ks2; x1 += k0 + 2u;
    TFR(13) TFR(15) TFR(26) TFR(6)
    x0 += k0;  x1 += k1 + 3u;
    TFR(17) TFR(29) TFR(16) TFR(24)
    x0 += k1;  x1 += ks2 + 4u;
    TFR(13) TFR(15) TFR(26) TFR(6)
    x0 += ks2; x1 += k0 + 5u;
#undef TFR
    o0 = x0; o1 = x1;
}

// XLA's f32 tanh rational approximation (Eigen-derived), FMA Horner.
__device__ __forceinline__ float tanh_xla(float x) {
    if (fabsf(x) < 0.0004f) return x;
    float xc = fmaxf(-7.90531110763549805f, fminf(7.90531110763549805f, x));
    float x2 = xc * xc;
    float p = -2.76076847742355e-16f;
    p = fmaf(p, x2,  2.00018790482477e-13f);
    p = fmaf(p, x2, -8.60467152213735e-11f);
    p = fmaf(p, x2,  5.12229709037114e-08f);
    p = fmaf(p, x2,  1.48572235717979e-05f);
    p = fmaf(p, x2,  6.37261928875436e-04f);
    p = fmaf(p, x2,  4.89352455891786e-03f);
    p = xc * p;
    float q = 1.19825839466702e-06f;
    q = fmaf(q, x2,  1.18534705686654e-04f);
    q = fmaf(q, x2,  2.26843463243900e-03f);
    q = fmaf(q, x2,  4.89352518554385e-03f);
    return p / q;
}

// bf16x2 pack/unpack: spins are {-1,0,+1} (zero low-16 mantissa) -> EXACT.
__device__ __forceinline__ uint32_t pack2(float a, float b) {
    return __byte_perm(__float_as_uint(a), __float_as_uint(b), 0x7632);
}
__device__ __forceinline__ float unpack_lo(uint32_t w) { return __uint_as_float(w << 16); }
__device__ __forceinline__ float unpack_hi(uint32_t w) { return __uint_as_float(w & 0xFFFF0000u); }

// ---- mbarrier / bulk-copy PTX helpers ----
__device__ __forceinline__ uint32_t smem_u32(const void* p) {
    return (uint32_t)__cvta_generic_to_shared(p);
}
__device__ __forceinline__ void mbar_init(uint32_t a, uint32_t cnt) {
    asm volatile("mbarrier.init.shared.b64 [%0], %1;" :: "r"(a), "r"(cnt) : "memory");
}
__device__ __forceinline__ void mbar_expect_tx(uint32_t a, uint32_t bytes) {
    asm volatile("mbarrier.arrive.expect_tx.shared.b64 _, [%0], %1;"
                 :: "r"(a), "r"(bytes) : "memory");
}
__device__ __forceinline__ void bulk_g2s(uint32_t dst, const void* src,
                                         uint32_t bytes, uint32_t mbar) {
    asm volatile(
        "cp.async.bulk.shared::cluster.global.mbarrier::complete_tx::bytes "
        "[%0], [%1], %2, [%3];"
        :: "r"(dst), "l"(src), "r"(bytes), "r"(mbar) : "memory");
}
__device__ __forceinline__ void mbar_wait(uint32_t a, uint32_t parity) {
    asm volatile(
        "{\n\t.reg .pred P;\n"
        "LW_%=:\n\t"
        "mbarrier.try_wait.parity.acquire.cta.shared::cta.b64 P, [%0], %1, 0x989680;\n\t"
        "@P bra.uni LD_%=;\n\t"
        "bra.uni LW_%=;\n"
        "LD_%=:\n\t}"
        :: "r"(a), "r"(parity) : "memory");
}

// ---------------------------------------------------------------------------
// Prep: dense J -> quad-packed transposed CSR. One warp per group-slot t;
// row = groups[t]. Ascending column order preserved (== reference order).
//   k <  FIXED -> d_colQ/d_valQ [g][k>>2][slot][k&3]  (zero-padded)
//   k >= FIXED -> d_csr[row][k]  (rare overflow; untouched slots stay 0)
// ---------------------------------------------------------------------------
__global__ void csr_kernel(const float* __restrict__ J,
                           const int* __restrict__ groups) {
    int t = (int)((blockIdx.x * blockDim.x + threadIdx.x) >> 5);
    if (t >= NN) return;
    int lane = threadIdx.x & 31;

    int g    = t / GSZ;
    int slot = t - g * GSZ;
    int row  = groups[t];
    const size_t gbase = (size_t)g * NQUAD * GSZPAD;   // quad-slot units

    const float4* Jr = reinterpret_cast<const float4*>(J + (size_t)row * NN);
    const int NV4 = NN / 4;                       // 1066 (NN % 4 == 0)

    int count = 0;
    for (int q0 = 0; q0 < NV4; q0 += 32) {
        int q = q0 + lane;
        float4 v = (q < NV4) ? Jr[q] : make_float4(0.f, 0.f, 0.f, 0.f);
        int n = (v.x != 0.f) + (v.y != 0.f) + (v.z != 0.f) + (v.w != 0.f);
        int incl = n;
        #pragma unroll
        for (int d = 1; d < 32; d <<= 1) {
            int o = __shfl_up_sync(0xffffffffu, incl, d);
            if (lane >= d) incl += o;
        }
        int p = count + incl - n;                 // exclusive offset
        int c = q * 4;
        #define EMIT(val, col)                                                  \
            if ((val) != 0.f) {                                                 \
                if (p < FIXED) {                                                \
                    size_t ix = (gbase + (size_t)(p >> 2) * GSZPAD + slot) * 4 + (p & 3); \
                    d_colQ[ix] = (uint16_t)(col);                               \
                    d_valQ[ix] = (val);                                         \
                } else if (p < MAXD) {                                          \
                    d_csr[row][p] =                                             \
                        make_uint2((uint32_t)(col), __float_as_uint(val));      \
                }                                                               \
                ++p;                                                            \
            }
        EMIT(v.x, c + 0) EMIT(v.y, c + 1) EMIT(v.z, c + 2) EMIT(v.w, c + 3)
        #undef EMIT
        count += __shfl_sync(0xffffffffu, incl, 31);
    }
    for (int k = count + lane; k < FIXED; k += 32) {   // exact +0 padding
        size_t ix = (gbase + (size_t)(k >> 2) * GSZPAD + slot) * 4 + (k & 3);
        d_colQ[ix] = 0; d_valQ[ix] = 0.0f;
    }
    if (lane == 0) d_deg[row] = (count < MAXD) ? count : MAXD;
}

// ---------------------------------------------------------------------------
// Main: one CTA per PAIR of batch rows; spins in SMEM packed bf16x2.
// CSR stream double-buffered through SMEM via cp.async.bulk + mbarrier,
// prefetched one phase ahead. Quad-packed records: per thread per phase
// 6 x LDS.64 (cols) + 6 x LDS.128 (vals) + 24 gathers. Overflow (deg>FIXED)
// prefetched at phase start, applied in ascending order -> bit-exact.
// ---------------------------------------------------------------------------
__global__ void __launch_bounds__(TPB, 1)
gibbs_kernel(const float* __restrict__ m_in, const float* __restrict__ H,
             const int* __restrict__ groups, const int* __restrict__ sn,
             float* __restrict__ m_out) {
    extern __shared__ uint8_t sm[];
    uint32_t* msh   = reinterpret_cast<uint32_t*>(sm + SM_MSH);
    uint32_t* skey  = reinterpret_cast<uint32_t*>(sm + SM_SKEY);   // [p][2]
    uint2*    scols = reinterpret_cast<uint2*>(sm + SM_COLS);      // 2 x NQUAD*GSZPAD
    float4*   svals = reinterpret_cast<float4*>(sm + SM_VALS);     // 2 x NQUAD*GSZPAD

    const uint32_t mbarA = smem_u32(sm + SM_MBAR);                 // mbar[2]
    const uint32_t colsA = smem_u32(sm + SM_COLS);
    const uint32_t valsA = smem_u32(sm + SM_VALS);

    const int b0  = 2 * blockIdx.x;
    const int b1  = b0 + 1;
    const int tid = threadIdx.x;

    int S = *sn; if (S > MAXS) S = MAXS; if (S < 0) S = 0;
    const int P = S * NGRP;

    for (int i = tid; i < NN; i += TPB)
        msh[i] = pack2(m_in[(size_t)b0 * NN + i], m_in[(size_t)b1 * NN + i]);

    // (sweep, group) keys: iter = tf(key42,(0,s)); group = tf(iter,(0,g))
    for (int u = tid; u < P; u += TPB) {
        int s = u / NGRP, g = u - s * NGRP;
        uint32_t ik0, ik1, gk0, gk1;
        tf2x32(0u, 42u, 0u, (uint32_t)s, ik0, ik1);
        tf2x32(ik0, ik1, 0u, (uint32_t)g, gk0, gk1);
        skey[2 * u + 0] = gk0; skey[2 * u + 1] = gk1;
    }

    // per-thread register cache per group
    const bool act = (tid < GSZ);
    int   nd[NGRP];
    float hh[NGRP];
    int   dg[NGRP];
    #pragma unroll
    for (int g = 0; g < NGRP; ++g) {
        int node = act ? groups[g * GSZ + tid] : 0;
        nd[g] = node;
        hh[g] = act ? H[node] : 0.0f;
        dg[g] = act ? d_deg[node] : 0;
    }

    if (tid == 0) { mbar_init(mbarA, 1); mbar_init(mbarA + 8, 1); }
    __syncthreads();

    // prologue: stage phase 0 into buffer 0
    if (tid == 0 && P > 0) {
        mbar_expect_tx(mbarA, STAGE_BYTES);
        bulk_g2s(colsA, d_colQ, COLS_BYTES, mbarA);
        bulk_g2s(valsA, d_valQ, VALS_BYTES, mbarA);
    }

    const uint32_t c0 = (uint32_t)(b0 * GSZ + tid);
    const uint32_t c1 = c0 + (uint32_t)GSZ;

    for (int s = 0; s < S; ++s) {
        #pragma unroll
        for (int g = 0; g < NGRP; ++g) {
            const int p = s * NGRP + g;
            // stage phase p+1 into the other buffer
            if (tid == 0 && p + 1 < P) {
                const int pn = p + 1, gn = pn & 7, bn = pn & 1;
                const uint32_t mb = mbarA + 8u * bn;
                mbar_expect_tx(mb, STAGE_BYTES);
                bulk_g2s(colsA + (uint32_t)bn * COLS_BYTES,
                         d_colQ + (size_t)gn * NQUAD * GSZPAD * 4, COLS_BYTES, mb);
                bulk_g2s(valsA + (uint32_t)bn * VALS_BYTES,
                         d_valQ + (size_t)gn * NQUAD * GSZPAD * 4, VALS_BYTES, mb);
            }

            uint32_t packed = 0u;
            int node = nd[g];
            int td   = dg[g];

            // overflow prefetch FIRST (rare; latency hidden under the RNG).
            // Unwritten d_csr slots are zero => exact +0 fmaf no-ops.
            uint2 ov0 = make_uint2(0u, 0u), ov1 = ov0, ov2 = ov0, ov3 = ov0;
            if (td > FIXED) {
                const uint2* ce = d_csr[node];
                ov0 = ce[FIXED + 0];
                ov1 = ce[FIXED + 1];
                ov2 = ce[FIXED + 2];
                ov3 = ce[FIXED + 3];
            }

            // wait for this phase's staged data (parity = use_count & 1)
            mbar_wait(mbarA + 8u * (p & 1), (uint32_t)((p >> 1) & 1));

            if (act) {
                const uint32_t k0 = skey[2 * p + 0];
                const uint32_t k1 = skey[2 * p + 1];
                uint32_t ya, yb, yc, yd;
                tf2x32(k0, k1, 0u, c0, ya, yb);
                tf2x32(k0, k1, 0u, c1, yc, yd);
                float r0 = (__uint_as_float(((ya ^ yb) >> 9) | 0x3f800000u) - 1.0f) * 2.0f - 1.0f;
                float r1 = (__uint_as_float(((yc ^ yd) >> 9) | 0x3f800000u) - 1.0f) * 2.0f - 1.0f;

                const uint2*  sc = scols + (size_t)(p & 1) * NQUAD * GSZPAD + tid;
                const float4* sv = svals + (size_t)(p & 1) * NQUAD * GSZPAD + tid;
                float a0 = 0.f, a1 = 0.f;
                #pragma unroll
                for (int j = 0; j < NQUAD; ++j) {
                    uint2  c4 = sc[j * GSZPAD];
                    float4 v4 = sv[j * GSZPAD];
                    uint32_t w;
                    w = msh[c4.x & 0xFFFFu];
                    a0 = fmaf(v4.x, unpack_lo(w), a0); a1 = fmaf(v4.x, unpack_hi(w), a1);
                    w = msh[c4.x >> 16];
                    a0 = fmaf(v4.y, unpack_lo(w), a0); a1 = fmaf(v4.y, unpack_hi(w), a1);
                    w = msh[c4.y & 0xFFFFu];
                    a0 = fmaf(v4.z, unpack_lo(w), a0); a1 = fmaf(v4.z, unpack_hi(w), a1);
                    w = msh[c4.y >> 16];
                    a0 = fmaf(v4.w, unpack_lo(w), a0); a1 = fmaf(v4.w, unpack_hi(w), a1);
                }
                if (td > FIXED) {                  // ~1.2% of nodes
                    #define APPLY(e) {                                     \
                        uint32_t w = msh[(e).x];                           \
                        float  vv  = __uint_as_float((e).y);               \
                        a0 = fmaf(vv, unpack_lo(w), a0);                   \
                        a1 = fmaf(vv, unpack_hi(w), a1); }
                    APPLY(ov0) APPLY(ov1) APPLY(ov2) APPLY(ov3)
                    #undef APPLY
                    if (td > FIXED + 4) {          // vanishing probability
                        for (int k = FIXED + 4; k < td; ++k) {
                            uint2 e = d_csr[node][k];
                            uint32_t w = msh[e.x];
                            float  vv  = __uint_as_float(e.y);
                            a0 = fmaf(vv, unpack_lo(w), a0);
                            a1 = fmaf(vv, unpack_hi(w), a1);
                        }
                    }
                }
                float d0 = tanh_xla(a0 + hh[g]) - r0;
                float d1 = tanh_xla(a1 + hh[g]) - r1;
                float s0 = (d0 > 0.f) ? 1.f : ((d0 < 0.f) ? -1.f : 0.f);
                float s1 = (d1 > 0.f) ? 1.f : ((d1 < 0.f) ? -1.f : 0.f);
                packed = pack2(s0, s1);            // exact for {-1,0,1}
            }
            __syncthreads();                      // all reads done
            if (act) msh[node] = packed;
            __syncthreads();                      // writes visible
        }
    }

    for (int i = tid; i < NN; i += TPB) {
        uint32_t w = msh[i];
        m_out[(size_t)b0 * NN + i] = unpack_lo(w);
        m_out[(size_t)b1 * NN + i] = unpack_hi(w);
    }
}

// ---------------------------------------------------------------------------
extern "C" void kernel_launch(void* const* d_in, const int* in_sizes, int n_in,
                              void* d_out, int out_size) {
    const float* m      = (const float*)d_in[0];
    const float* J      = (const float*)d_in[1];
    const float* H      = (const float*)d_in[2];
    const int*   groups = (const int*)  d_in[3];
    const int*   sn     = (const int*)  d_in[4];

    static int smem_set = 0;
    if (!smem_set) {
        cudaFuncSetAttribute(gibbs_kernel,
                             cudaFuncAttributeMaxDynamicSharedMemorySize, SM_TOTAL);
        smem_set = 1;
    }

    csr_kernel<<<(NN + 7) / 8, 256>>>(J, groups);    // 1 warp per group-slot
    gibbs_kernel<<<BB / 2, TPB, SM_TOTAL>>>(m, H, groups, sn, (float*)d_out);
}

// round 11
// speedup vs baseline: 1.1459x; 1.1074x over previous
#include <cuda_runtime.h>
#include <stdint.h>

// Problem constants (fixed by setup_inputs)
#define NN     4264    // all_node_num
#define BB     256     // batch
#define NGRP   8       // color groups
#define GSZ    533     // nodes per group
#define GSZPAD 536     // padded slot stride (keeps every region 16B-aligned)
#define FIXED  24      // CSR entries per node (zero-padded)
#define NQUAD  (FIXED/4)
#define MAXD   48      // hard cap on stored degree
#define MAXS   128     // max sweeps supported
#define TPB    544     // 17 warps: one node per thread (533 active)

#define COLS_BYTES (NQUAD * GSZPAD * 8)       // 25728 (uint2 per quad-slot), %16==0
#define VALS_BYTES (NQUAD * GSZPAD * 16)      // 51456 (float4 per quad-slot), %16==0
#define STAGE_BYTES (COLS_BYTES + VALS_BYTES)

// Dynamic smem layout (all region offsets multiples of 16)
#define SM_MBAR   0
#define SM_MSH    16
#define SM_SKEY   (SM_MSH + NN * 4)                       // 17072
#define SM_COLS   (SM_SKEY + MAXS * NGRP * 8)             // 25264
#define SM_VALS   (SM_COLS + 2 * COLS_BYTES)              // 76720
#define SM_TOTAL  (SM_VALS + 2 * VALS_BYTES)              // 179632 (<227KB opt-in)

// Scratch (static device globals — no allocation)
__device__ int      d_deg[NN];
__device__ uint2    d_csr[NN][MAXD];              // overflow entries (k >= FIXED); rest 0
__device__ __align__(16) uint16_t d_colQ[NGRP * NQUAD * GSZPAD * 4]; // [g][q][slot][4]
__device__ __align__(16) float    d_valQ[NGRP * NQUAD * GSZPAD * 4]; // [g][q][slot][4]

// ---------------------------------------------------------------------------
// Threefry-2x32 (20 rounds), bit-exact vs jax._src.prng.threefry2x32
// ---------------------------------------------------------------------------
__device__ __forceinline__ void tf2x32(uint32_t k0, uint32_t k1,
                                       uint32_t x0, uint32_t x1,
                                       uint32_t& o0, uint32_t& o1) {
    uint32_t ks2 = k0 ^ k1 ^ 0x1BD11BDAu;
    x0 += k0; x1 += k1;
#define TFR(r) { x0 += x1; x1 = __funnelshift_l(x1, x1, r); x1 ^= x0; }
    TFR(13) TFR(15) TFR(26) TFR(6)
    x0 += k1;  x1 += ks2 + 1u;
    TFR(17) TFR(29) TFR(16) TFR(24)
    x0 += ks2; x1 += k0 + 2u;
    TFR(13) TFR(15) TFR(26) TFR(6)
    x0 += k0;  x1 += k1 + 3u;
    TFR(17) TFR(29) TFR(16) TFR(24)
    x0 += k1;  x1 += ks2 + 4u;
    TFR(13) TFR(15) TFR(26) TFR(6)
    x0 += ks2; x1 += k0 + 5u;
#undef TFR
    o0 = x0; o1 = x1;
}

// XLA's f32 tanh rational approximation (Eigen-derived), FMA Horner.
// BRANCHLESS: rational always computed, small-|x| case selected at the end.
// Identical values to the branching version for every input.
__device__ __forceinline__ float tanh_xla(float x) {
    float xc = fmaxf(-7.90531110763549805f, fminf(7.90531110763549805f, x));
    float x2 = xc * xc;
    float p = -2.76076847742355e-16f;
    p = fmaf(p, x2,  2.00018790482477e-13f);
    p = fmaf(p, x2, -8.60467152213735e-11f);
    p = fmaf(p, x2,  5.12229709037114e-08f);
    p = fmaf(p, x2,  1.48572235717979e-05f);
    p = fmaf(p, x2,  6.37261928875436e-04f);
    p = fmaf(p, x2,  4.89352455891786e-03f);
    p = xc * p;
    float q = 1.19825839466702e-06f;
    q = fmaf(q, x2,  1.18534705686654e-04f);
    q = fmaf(q, x2,  2.26843463243900e-03f);
    q = fmaf(q, x2,  4.89352518554385e-03f);
    float rat = p / q;
    return (fabsf(x) < 0.0004f) ? x : rat;
}

// bf16x2 pack/unpack: spins are {-1,0,+1} (zero low-16 mantissa) -> EXACT.
__device__ __forceinline__ uint32_t pack2(float a, float b) {
    return __byte_perm(__float_as_uint(a), __float_as_uint(b), 0x7632);
}
__device__ __forceinline__ float unpack_lo(uint32_t w) { return __uint_as_float(w << 16); }
__device__ __forceinline__ float unpack_hi(uint32_t w) { return __uint_as_float(w & 0xFFFF0000u); }

// ---- mbarrier / bulk-copy PTX helpers ----
__device__ __forceinline__ uint32_t smem_u32(const void* p) {
    return (uint32_t)__cvta_generic_to_shared(p);
}
__device__ __forceinline__ void mbar_init(uint32_t a, uint32_t cnt) {
    asm volatile("mbarrier.init.shared.b64 [%0], %1;" :: "r"(a), "r"(cnt) : "memory");
}
__device__ __forceinline__ void mbar_expect_tx(uint32_t a, uint32_t bytes) {
    asm volatile("mbarrier.arrive.expect_tx.shared.b64 _, [%0], %1;"
                 :: "r"(a), "r"(bytes) : "memory");
}
__device__ __forceinline__ void bulk_g2s(uint32_t dst, const void* src,
                                         uint32_t bytes, uint32_t mbar) {
    asm volatile(
        "cp.async.bulk.shared::cluster.global.mbarrier::complete_tx::bytes "
        "[%0], [%1], %2, [%3];"
        :: "r"(dst), "l"(src), "r"(bytes), "r"(mbar) : "memory");
}
__device__ __forceinline__ void mbar_wait(uint32_t a, uint32_t parity) {
    asm volatile(
        "{\n\t.reg .pred P;\n"
        "LW_%=:\n\t"
        "mbarrier.try_wait.parity.acquire.cta.shared::cta.b64 P, [%0], %1, 0x989680;\n\t"
        "@P bra.uni LD_%=;\n\t"
        "bra.uni LW_%=;\n"
        "LD_%=:\n\t}"
        :: "r"(a), "r"(parity) : "memory");
}

// ---------------------------------------------------------------------------
// Prep: dense J -> quad-packed transposed CSR. One warp per group-slot t;
// row = groups[t]. Ascending column order preserved (== reference order).
//   k <  FIXED -> d_colQ/d_valQ [g][k>>2][slot][k&3]  (zero-padded)
//   k >= FIXED -> d_csr[row][k]  (rare overflow; untouched slots stay 0)
// ---------------------------------------------------------------------------
__global__ void csr_kernel(const float* __restrict__ J,
                           const int* __restrict__ groups) {
    int t = (int)((blockIdx.x * blockDim.x + threadIdx.x) >> 5);
    if (t >= NN) return;
    int lane = threadIdx.x & 31;

    int g    = t / GSZ;
    int slot = t - g * GSZ;
    int row  = groups[t];
    const size_t gbase = (size_t)g * NQUAD * GSZPAD;   // quad-slot units

    const float4* Jr = reinterpret_cast<const float4*>(J + (size_t)row * NN);
    const int NV4 = NN / 4;                       // 1066 (NN % 4 == 0)

    int count = 0;
    for (int q0 = 0; q0 < NV4; q0 += 32) {
        int q = q0 + lane;
        float4 v = (q < NV4) ? Jr[q] : make_float4(0.f, 0.f, 0.f, 0.f);
        int n = (v.x != 0.f) + (v.y != 0.f) + (v.z != 0.f) + (v.w != 0.f);
        int incl = n;
        #pragma unroll
        for (int d = 1; d < 32; d <<= 1) {
            int o = __shfl_up_sync(0xffffffffu, incl, d);
            if (lane >= d) incl += o;
        }
        int p = count + incl - n;                 // exclusive offset
        int c = q * 4;
        #define EMIT(val, col)                                                  \
            if ((val) != 0.f) {                                                 \
                if (p < FIXED) {                                                \
                    size_t ix = (gbase + (size_t)(p >> 2) * GSZPAD + slot) * 4 + (p & 3); \
                    d_colQ[ix] = (uint16_t)(col);                               \
                    d_valQ[ix] = (val);                                         \
                } else if (p < MAXD) {                                          \
                    d_csr[row][p] =                                             \
                        make_uint2((uint32_t)(col), __float_as_uint(val));      \
                }                                                               \
                ++p;                                                            \
            }
        EMIT(v.x, c + 0) EMIT(v.y, c + 1) EMIT(v.z, c + 2) EMIT(v.w, c + 3)
        #undef EMIT
        count += __shfl_sync(0xffffffffu, incl, 31);
    }
    for (int k = count + lane; k < FIXED; k += 32) {   // exact +0 padding
        size_t ix = (gbase + (size_t)(k >> 2) * GSZPAD + slot) * 4 + (k & 3);
        d_colQ[ix] = 0; d_valQ[ix] = 0.0f;
    }
    if (lane == 0) d_deg[row] = (count < MAXD) ? count : MAXD;
}

// ---------------------------------------------------------------------------
// Main: one CTA per PAIR of batch rows; spins in SMEM packed bf16x2.
// CSR stream double-buffered through SMEM via cp.async.bulk + mbarrier.
// Per-phase order: TMA stage by INACTIVE lane 533 | RNG (pure ALU, runs in
// the barrier-drain / TRYWAIT shadow) | overflow prefetch | mbar_wait |
// gathers (quads past a node's degree: stream LDS predicated off, cols
// forced 0 -> broadcast gathers, vals 0 -> exact +0 fmaf) | sign | barriers.
// Bit-identical math to prior passing kernels.
// ---------------------------------------------------------------------------
__global__ void __launch_bounds__(TPB, 1)
gibbs_kernel(const float* __restrict__ m_in, const float* __restrict__ H,
             const int* __restrict__ groups, const int* __restrict__ sn,
             float* __restrict__ m_out) {
    extern __shared__ uint8_t sm[];
    uint32_t* msh   = reinterpret_cast<uint32_t*>(sm + SM_MSH);
    uint32_t* skey  = reinterpret_cast<uint32_t*>(sm + SM_SKEY);   // [p][2]
    uint2*    scols = reinterpret_cast<uint2*>(sm + SM_COLS);      // 2 x NQUAD*GSZPAD
    float4*   svals = reinterpret_cast<float4*>(sm + SM_VALS);     // 2 x NQUAD*GSZPAD

    const uint32_t mbarA = smem_u32(sm + SM_MBAR);                 // mbar[2]
    const uint32_t colsA = smem_u32(sm + SM_COLS);
    const uint32_t valsA = smem_u32(sm + SM_VALS);

    const int b0  = 2 * blockIdx.x;
    const int b1  = b0 + 1;
    const int tid = threadIdx.x;

    int S = *sn; if (S > MAXS) S = MAXS; if (S < 0) S = 0;
    const int P = S * NGRP;

    for (int i = tid; i < NN; i += TPB)
        msh[i] = pack2(m_in[(size_t)b0 * NN + i], m_in[(size_t)b1 * NN + i]);

    // (sweep, group) keys: iter = tf(key42,(0,s)); group = tf(iter,(0,g))
    for (int u = tid; u < P; u += TPB) {
        int s = u / NGRP, g = u - s * NGRP;
        uint32_t ik0, ik1, gk0, gk1;
        tf2x32(0u, 42u, 0u, (uint32_t)s, ik0, ik1);
        tf2x32(ik0, ik1, 0u, (uint32_t)g, gk0, gk1);
        skey[2 * u + 0] = gk0; skey[2 * u + 1] = gk1;
    }

    // per-thread register cache per group
    const bool act = (tid < GSZ);
    int   nd[NGRP];
    float hh[NGRP];
    int   dg[NGRP];
    #pragma unroll
    for (int g = 0; g < NGRP; ++g) {
        int node = act ? groups[g * GSZ + tid] : 0;
        nd[g] = node;
        hh[g] = act ? H[node] : 0.0f;
        dg[g] = act ? d_deg[node] : 0;
    }

    if (tid == 0) { mbar_init(mbarA, 1); mbar_init(mbarA + 8, 1); }
    __syncthreads();

    // prologue: stage phase 0 into buffer 0 (issued from an inactive lane)
    if (tid == GSZ && P > 0) {
        mbar_expect_tx(mbarA, STAGE_BYTES);
        bulk_g2s(colsA, d_colQ, COLS_BYTES, mbarA);
        bulk_g2s(valsA, d_valQ, VALS_BYTES, mbarA);
    }

    const uint32_t c0 = (uint32_t)(b0 * GSZ + tid);
    const uint32_t c1 = c0 + (uint32_t)GSZ;

    for (int s = 0; s < S; ++s) {
        #pragma unroll
        for (int g = 0; g < NGRP; ++g) {
            const int p = s * NGRP + g;
            // stage phase p+1 (inactive tail lane -> no skew on active warps)
            if (tid == GSZ && p + 1 < P) {
                const int pn = p + 1, gn = pn & 7, bn = pn & 1;
                const uint32_t mb = mbarA + 8u * bn;
                mbar_expect_tx(mb, STAGE_BYTES);
                bulk_g2s(colsA + (uint32_t)bn * COLS_BYTES,
                         d_colQ + (size_t)gn * NQUAD * GSZPAD * 4, COLS_BYTES, mb);
                bulk_g2s(valsA + (uint32_t)bn * VALS_BYTES,
                         d_valQ + (size_t)gn * NQUAD * GSZPAD * 4, VALS_BYTES, mb);
            }

            uint32_t packed = 0u;
            int node = nd[g];
            int td   = dg[g];

            // RNG first: pure ALU, independent of staged data -> executes in
            // the barrier-drain / mbar TRYWAIT shadow.
            float r0 = 0.f, r1 = 0.f;
            if (act) {
                const uint32_t k0 = skey[2 * p + 0];
                const uint32_t k1 = skey[2 * p + 1];
                uint32_t ya, yb, yc, yd;
                tf2x32(k0, k1, 0u, c0, ya, yb);
                tf2x32(k0, k1, 0u, c1, yc, yd);
                r0 = (__uint_as_float(((ya ^ yb) >> 9) | 0x3f800000u) - 1.0f) * 2.0f - 1.0f;
                r1 = (__uint_as_float(((yc ^ yd) >> 9) | 0x3f800000u) - 1.0f) * 2.0f - 1.0f;
            }

            // overflow prefetch (rare). Unwritten d_csr slots are zero.
            uint2 ov0 = make_uint2(0u, 0u), ov1 = ov0, ov2 = ov0, ov3 = ov0;
            if (td > FIXED) {
                const uint2* ce = d_csr[node];
                ov0 = ce[FIXED + 0];
                ov1 = ce[FIXED + 1];
                ov2 = ce[FIXED + 2];
                ov3 = ce[FIXED + 3];
            }

            // wait for this phase's staged data (parity = use_count & 1)
            mbar_wait(mbarA + 8u * (p & 1), (uint32_t)((p >> 1) & 1));

            if (act) {
                const uint2*  sc = scols + (size_t)(p & 1) * NQUAD * GSZPAD + tid;
                const float4* sv = svals + (size_t)(p & 1) * NQUAD * GSZPAD + tid;
                float a0 = 0.f, a1 = 0.f;
                #pragma unroll
                for (int j = 0; j < NQUAD; ++j) {
                    // Quads past this node's degree: skip the stream LDS
                    // (predicated off) and use cols=0 (broadcast gather of
                    // msh[0] -> no crossbar conflicts) with vals=0 (+0 fmaf).
                    uint2  c4 = make_uint2(0u, 0u);
                    float4 v4 = make_float4(0.f, 0.f, 0.f, 0.f);
                    if (4 * j < td) {
                        c4 = sc[j * GSZPAD];
                        v4 = sv[j * GSZPAD];
                    }
                    uint32_t w;
                    w = msh[c4.x & 0xFFFFu];
                    a0 = fmaf(v4.x, unpack_lo(w), a0); a1 = fmaf(v4.x, unpack_hi(w), a1);
                    w = msh[c4.x >> 16];
                    a0 = fmaf(v4.y, unpack_lo(w), a0); a1 = fmaf(v4.y, unpack_hi(w), a1);
                    w = msh[c4.y & 0xFFFFu];
                    a0 = fmaf(v4.z, unpack_lo(w), a0); a1 = fmaf(v4.z, unpack_hi(w), a1);
                    w = msh[c4.y >> 16];
                    a0 = fmaf(v4.w, unpack_lo(w), a0); a1 = fmaf(v4.w, unpack_hi(w), a1);
                }
                if (td > FIXED) {                  // ~1.2% of nodes
                    #define APPLY(e) {                                     \
                        uint32_t w = msh[(e).x];                           \
                        float  vv  = __uint_as_float((e).y);               \
                        a0 = fmaf(vv, unpack_lo(w), a0);                   \
                        a1 = fmaf(vv, unpack_hi(w), a1); }
                    APPLY(ov0) APPLY(ov1) APPLY(ov2) APPLY(ov3)
                    #undef APPLY
                    if (td > FIXED + 4) {          // vanishing probability
                        for (int k = FIXED + 4; k < td; ++k) {
                            uint2 e = d_csr[node][k];
                            uint32_t w = msh[e.x];
                            float  vv  = __uint_as_float(e.y);
                            a0 = fmaf(vv, unpack_lo(w), a0);
                            a1 = fmaf(vv, unpack_hi(w), a1);
                        }
                    }
                }
                float d0 = tanh_xla(a0 + hh[g]) - r0;
                float d1 = tanh_xla(a1 + hh[g]) - r1;
                float s0 = (d0 > 0.f) ? 1.f : ((d0 < 0.f) ? -1.f : 0.f);
                float s1 = (d1 > 0.f) ? 1.f : ((d1 < 0.f) ? -1.f : 0.f);
                packed = pack2(s0, s1);            // exact for {-1,0,1}
            }
            __syncthreads();                      // all reads done
            if (act) msh[node] = packed;
            __syncthreads();                      // writes visible
        }
    }

    for (int i = tid; i < NN; i += TPB) {
        uint32_t w = msh[i];
        m_out[(size_t)b0 * NN + i] = unpack_lo(w);
        m_out[(size_t)b1 * NN + i] = unpack_hi(w);
    }
}

// ---------------------------------------------------------------------------
extern "C" void kernel_launch(void* const* d_in, const int* in_sizes, int n_in,
                              void* d_out, int out_size) {
    const float* m      = (const float*)d_in[0];
    const float* J      = (const float*)d_in[1];
    const float* H      = (const float*)d_in[2];
    const int*   groups = (const int*)  d_in[3];
    const int*   sn     = (const int*)  d_in[4];

    static int smem_set = 0;
    if (!smem_set) {
        cudaFuncSetAttribute(gibbs_kernel,
                             cudaFuncAttributeMaxDynamicSharedMemorySize, SM_TOTAL);
        smem_set = 1;
    }

    csr_kernel<<<(NN + 7) / 8, 256>>>(J, groups);    // 1 warp per group-slot
    gibbs_kernel<<<BB / 2, TPB, SM_TOTAL>>>(m, H, groups, sn, (float*)d_out);
}